// round 2
// baseline (speedup 1.0000x reference)
#include <cuda_runtime.h>
#include <math.h>

#define NCLS   20
#define NBINS  16
#define NANCH  21824
#define BATCH  16
#define MGT    32
#define NGT    (BATCH*MGT)

// global accumulators / scratch (no device mallocs allowed)
__device__ double g_qfl, g_dfl, g_giou;
__device__ int    g_pos;
__device__ float  g_thr[NGT];

__global__ void init_kernel() {
    g_qfl = 0.0; g_dfl = 0.0; g_giou = 0.0; g_pos = 0;
}

// ---------------------------------------------------------------------------
// Phase A: ATSS threshold per GT.
// 64 blocks x 256 threads; each warp owns one GT (512 GTs total).
// Anchors streamed through shared memory tiles; each lane keeps a sorted
// top-9 (smallest squared center distance), then a 9-round warp arg-min merge
// selects the global top-9; lane 0 computes their IoUs -> thr = mean + std(ddof=1).
// ---------------------------------------------------------------------------
__global__ void thr_kernel(const float4* __restrict__ anchors,
                           const float4* __restrict__ gt_boxes) {
    __shared__ float4 sA[2048];
    const int warp = threadIdx.x >> 5;
    const int lane = threadIdx.x & 31;
    const int g = blockIdx.x * 8 + warp;           // 0..511

    const float4 gt = __ldg(&gt_boxes[g]);
    const float gcx = 0.5f * (gt.x + gt.z);
    const float gcy = 0.5f * (gt.y + gt.w);

    float d[9]; int id[9];
#pragma unroll
    for (int k = 0; k < 9; k++) { d[k] = 3.4e38f; id[k] = -1; }

    for (int base = 0; base < NANCH; base += 2048) {
        const int n = min(2048, NANCH - base);
        __syncthreads();
        for (int i = threadIdx.x; i < n; i += 256) sA[i] = anchors[base + i];
        __syncthreads();
        for (int i = lane; i < n; i += 32) {
            float4 a = sA[i];
            float dx = 0.5f * (a.x + a.z) - gcx;
            float dy = 0.5f * (a.y + a.w) - gcy;
            float d2 = dx * dx + dy * dy;
            if (d2 < d[8]) {
                float vd = d2; int vi = base + i;
#pragma unroll
                for (int k = 0; k < 9; k++) {
                    if (vd < d[k]) {
                        float tv = d[k]; d[k] = vd; vd = tv;
                        int   ti = id[k]; id[k] = vi; vi = ti;
                    }
                }
            }
        }
    }

    // warp merge: 9 rounds of arg-min over per-lane sorted lists
    int p = 0;
    float vals[9];
#pragma unroll
    for (int r = 0; r < 9; r++) {
        float cv = 3.4e38f; int ci = 0x7fffffff;
#pragma unroll
        for (int k = 0; k < 9; k++) if (p == k) { cv = d[k]; ci = id[k]; }
#pragma unroll
        for (int off = 16; off > 0; off >>= 1) {
            float od = __shfl_xor_sync(0xffffffffu, cv, off);
            int   oi = __shfl_xor_sync(0xffffffffu, ci, off);
            if (od < cv || (od == cv && oi < ci)) { cv = od; ci = oi; }
        }
        bool mine = false;
#pragma unroll
        for (int k = 0; k < 9; k++) if (p == k && id[k] == ci) mine = true;
        if (mine) p++;
        if (lane == 0) {
            float4 a = __ldg(&anchors[ci]);
            float aa = (a.z - a.x) * (a.w - a.y);
            float ab = (gt.z - gt.x) * (gt.w - gt.y);
            float lx = fmaxf(a.x, gt.x), ly = fmaxf(a.y, gt.y);
            float rx = fminf(a.z, gt.z), ry = fminf(a.w, gt.w);
            float iw = fmaxf(rx - lx, 0.f), ih = fmaxf(ry - ly, 0.f);
            float inter = iw * ih;
            float uni = aa + ab - inter;
            vals[r] = inter / fmaxf(uni, 1e-9f);
        }
    }

    if (lane == 0) {
        float s = 0.f;
#pragma unroll
        for (int k = 0; k < 9; k++) s += vals[k];
        float mean = s / 9.0f;
        float vs = 0.f;
#pragma unroll
        for (int k = 0; k < 9; k++) { float t = vals[k] - mean; vs += t * t; }
        g_thr[g] = mean + sqrtf(vs / 8.0f);
    }
}

// ---------------------------------------------------------------------------
// Phase B: fused match + QFL + DFL + GIoU. One thread per (b, n).
// grid = (ceil(N/128), B), block = 128.
// reg_preds is only touched for positive anchors (sparse).
// ---------------------------------------------------------------------------
__global__ void loss_kernel(const float* __restrict__ cls_preds,
                            const float* __restrict__ reg_preds,
                            const float4* __restrict__ anchors,
                            const float4* __restrict__ gt_boxes,
                            const int* __restrict__ gt_labels) {
    __shared__ float4 sGT[MGT];
    __shared__ float  sThr[MGT];
    __shared__ int    sLab[MGT];
    const int b = blockIdx.y;
    if (threadIdx.x < MGT) {
        sGT[threadIdx.x]  = gt_boxes[b * MGT + threadIdx.x];
        sThr[threadIdx.x] = g_thr[b * MGT + threadIdx.x];
        sLab[threadIdx.x] = gt_labels[b * MGT + threadIdx.x];
    }
    __syncthreads();

    const int n = blockIdx.x * blockDim.x + threadIdx.x;
    float qfl = 0.f, dfl = 0.f, giou_l = 0.f;
    int posi = 0;

    if (n < NANCH) {
        float4 a = __ldg(&anchors[n]);
        float aw = a.z - a.x, ah = a.w - a.y;
        float acx = a.x + 0.5f * aw, acy = a.y + 0.5f * ah;
        float area_a = aw * ah;

        int matched = -1; float seliou = 0.f;
        for (int m = 0; m < MGT; m++) {
            float4 gbx = sGT[m];
            float ab = (gbx.z - gbx.x) * (gbx.w - gbx.y);
            float lx = fmaxf(a.x, gbx.x), ly = fmaxf(a.y, gbx.y);
            float rx = fminf(a.z, gbx.z), ry = fminf(a.w, gbx.w);
            float iw = fmaxf(rx - lx, 0.f), ih = fmaxf(ry - ly, 0.f);
            float inter = iw * ih;
            float uni = area_a + ab - inter;
            float iou = inter / fmaxf(uni, 1e-9f);
            bool inside = (acx >= gbx.x) && (acx <= gbx.z) &&
                          (acy >= gbx.y) && (acy <= gbx.w);
            if (inside && iou >= sThr[m]) { matched = m; seliou = iou; }
        }
        const bool pos = matched >= 0;
        posi = pos ? 1 : 0;
        const float it = pos ? seliou : 0.f;
        const int cls_t = pos ? sLab[matched] : 0;
        float4 rt = pos ? sGT[matched] : make_float4(0.f, 0.f, 0.f, 0.f);

        // ---- Quality Focal Loss over 20 classes ----
        const float4* cp = (const float4*)(cls_preds + ((size_t)b * NANCH + n) * NCLS);
#pragma unroll
        for (int v = 0; v < 5; v++) {
            float4 xv = __ldg(&cp[v]);
            float xs[4] = { xv.x, xv.y, xv.z, xv.w };
#pragma unroll
            for (int j = 0; j < 4; j++) {
                const int c = v * 4 + j;
                float x = xs[j];
                float t = (c == cls_t) ? 1.f : 0.f;
                float ax = fabsf(x);
                float e = expf(-ax);
                float bce = fmaxf(x, 0.f) - x * t + log1pf(e);
                float psig = ((x >= 0.f) ? 1.f : e) / (1.f + e);
                float pt = (t > 0.f) ? psig : (1.f - psig);
                float w = it * (1.f - pt) + (1.f - it) * pt;
                qfl += w * w * bce;
            }
        }

        // ---- DFL + decode + GIoU: positives only ----
        if (pos) {
            const float4* rp = (const float4*)(reg_preds + ((size_t)b * NANCH + n) * 4 * NBINS);
            float rts[4] = { rt.x, rt.y, rt.z, rt.w };
            float delta[4];
#pragma unroll
            for (int s = 0; s < 4; s++) {
                float l[16];
#pragma unroll
                for (int v = 0; v < 4; v++) {
                    float4 lv = __ldg(&rp[s * 4 + v]);
                    l[v * 4 + 0] = lv.x; l[v * 4 + 1] = lv.y;
                    l[v * 4 + 2] = lv.z; l[v * 4 + 3] = lv.w;
                }
                float mx = l[0];
#pragma unroll
                for (int k = 1; k < 16; k++) mx = fmaxf(mx, l[k]);

                float ts = rts[s] * 15.f;
                int li = (int)ts; li = max(0, min(li, 14));
                int ri = li + 1;
                float wr = ts - (float)li, wl = 1.f - wr;

                float se = 0.f, ne = 0.f, lli = 0.f, lri = 0.f;
#pragma unroll
                for (int k = 0; k < 16; k++) {
                    float ek = expf(l[k] - mx);
                    se += ek; ne += ek * (float)k;
                    if (k == li) lli = l[k];
                    if (k == ri) lri = l[k];
                }
                float lz = mx + logf(se);
                dfl += -(wl * (lli - lz) + wr * (lri - lz));
                delta[s] = ne / (se * 15.f);
            }
            // delta2bbox
            float pcx = delta[0] * aw + acx;
            float pcy = delta[1] * ah + acy;
            float pw = expf(delta[2]) * aw;
            float ph = expf(delta[3]) * ah;
            float px1 = pcx - 0.5f * pw, py1 = pcy - 0.5f * ph;
            float px2 = pcx + 0.5f * pw, py2 = pcy + 0.5f * ph;
            // elementwise giou
            float lx = fmaxf(px1, rt.x), ly = fmaxf(py1, rt.y);
            float rx = fminf(px2, rt.z), ry = fminf(py2, rt.w);
            float iw = fmaxf(rx - lx, 0.f), ih = fmaxf(ry - ly, 0.f);
            float inter = iw * ih;
            float pa = (px2 - px1) * (py2 - py1);
            float ga = (rt.z - rt.x) * (rt.w - rt.y);
            float uni = pa + ga - inter;
            float iou = inter / fmaxf(uni, 1e-9f);
            float ex1 = fminf(px1, rt.x), ey1 = fminf(py1, rt.y);
            float ex2 = fmaxf(px2, rt.z), ey2 = fmaxf(py2, rt.w);
            float ew = fmaxf(ex2 - ex1, 0.f), eh = fmaxf(ey2 - ey1, 0.f);
            float enc = ew * eh;
            float gv = iou - (enc - uni) / fmaxf(enc, 1e-9f);
            giou_l = 1.f - gv;
        }
    }

    // ---- reduction: warp -> block -> global double atomics ----
#pragma unroll
    for (int off = 16; off > 0; off >>= 1) {
        qfl    += __shfl_xor_sync(0xffffffffu, qfl,    off);
        dfl    += __shfl_xor_sync(0xffffffffu, dfl,    off);
        giou_l += __shfl_xor_sync(0xffffffffu, giou_l, off);
        posi   += __shfl_xor_sync(0xffffffffu, posi,   off);
    }
    __shared__ float rq[4], rd[4], rg[4];
    __shared__ int   rp_[4];
    const int warp = threadIdx.x >> 5;
    const int lane = threadIdx.x & 31;
    if (lane == 0) { rq[warp] = qfl; rd[warp] = dfl; rg[warp] = giou_l; rp_[warp] = posi; }
    __syncthreads();
    if (threadIdx.x == 0) {
        float q = rq[0] + rq[1] + rq[2] + rq[3];
        float dd = rd[0] + rd[1] + rd[2] + rd[3];
        float gg = rg[0] + rg[1] + rg[2] + rg[3];
        int   pp = rp_[0] + rp_[1] + rp_[2] + rp_[3];
        if (q  != 0.f) atomicAdd(&g_qfl,  (double)q);
        if (dd != 0.f) atomicAdd(&g_dfl,  (double)dd);
        if (gg != 0.f) atomicAdd(&g_giou, (double)gg);
        if (pp != 0)   atomicAdd(&g_pos,  pp);
    }
}

__global__ void final_kernel(float* __restrict__ out) {
    int pos = g_pos;
    double npc = (double)max(pos, 1);
    double q  = g_qfl / npc;
    double df = g_dfl / (double)max(4 * pos, 1);
    df = fmin(fmax(df, 0.0), 1.0);
    double gi = g_giou / npc;
    out[0] = (float)(q + df + gi);
    out[1] = (float)q;
    out[2] = (float)df;
    out[3] = (float)gi;
}

extern "C" void kernel_launch(void* const* d_in, const int* in_sizes, int n_in,
                              void* d_out, int out_size) {
    const float*  cls_preds = (const float*)d_in[0];
    const float*  reg_preds = (const float*)d_in[1];
    const float4* anchors   = (const float4*)d_in[2];
    const float4* gt_boxes  = (const float4*)d_in[3];
    const int*    gt_labels = (const int*)d_in[4];
    float* out = (float*)d_out;

    init_kernel<<<1, 1>>>();
    thr_kernel<<<64, 256>>>(anchors, gt_boxes);
    dim3 grid((NANCH + 127) / 128, BATCH);
    loss_kernel<<<grid, 128>>>(cls_preds, reg_preds, anchors, gt_boxes, gt_labels);
    final_kernel<<<1, 1>>>(out);
}

// round 5
// speedup vs baseline: 2.3751x; 2.3751x over previous
#include <cuda_runtime.h>
#include <math.h>

#define NCLS   20
#define NBINS  16
#define NANCH  21824
#define BATCH  16
#define MGT    32
#define NGT    (BATCH*MGT)

#define LOSS_BLK   256
#define LOSS_GX    ((NANCH + LOSS_BLK - 1) / LOSS_BLK)   // 86

// global accumulators / scratch (no device mallocs allowed)
__device__ double g_qfl, g_dfl, g_giou;
__device__ int    g_pos;
__device__ float  g_thr[NGT];

// ---------------------------------------------------------------------------
// Phase A: ATSS threshold, one THREAD per GT using analytic grid candidates.
// The 9 nearest anchors to any point lie within the 5x5 cell window around
// the containing cell at every level (anchor centers are regular grids).
// Enumerate 5 levels x 25 cells = 125 candidates, keep lexicographic top-9 by
// (norm, index) exactly like jax.lax.top_k tie-breaking, then thr = mean+std.
// Also zeroes the global accumulators (runs before loss_kernel).
// ---------------------------------------------------------------------------
__global__ void thr_kernel(const float4* __restrict__ gt_boxes) {
    const int g = blockIdx.x * blockDim.x + threadIdx.x;
    if (g == 0) { g_qfl = 0.0; g_dfl = 0.0; g_giou = 0.0; g_pos = 0; }
    if (g >= NGT) return;

    const float4 gt = __ldg(&gt_boxes[g]);
    const float gcx = 0.5f * (gt.x + gt.z);
    const float gcy = 0.5f * (gt.y + gt.w);

    const int   ns[5]   = {128, 64, 32, 16, 8};
    const float ss[5]   = {8.f, 16.f, 32.f, 64.f, 128.f};
    const int   offs[5] = {0, 16384, 20480, 21504, 21760};

    float td[9]; int ti[9];
#pragma unroll
    for (int k = 0; k < 9; k++) { td[k] = 3.4e38f; ti[k] = 0x7fffffff; }

#pragma unroll
    for (int l = 0; l < 5; l++) {
        const int n = ns[l];
        const float s = ss[l];
        int jcx = (int)floorf(gcx / s);
        int jcy = (int)floorf(gcy / s);
        int lx0 = min(max(jcx - 2, 0), n - 5);
        int ly0 = min(max(jcy - 2, 0), n - 5);
#pragma unroll
        for (int dy = 0; dy < 5; dy++) {
            const int iy = ly0 + dy;
            const float cy = (iy + 0.5f) * s;
            const float ddy = cy - gcy;
            const float ddy2 = __fmul_rn(ddy, ddy);
#pragma unroll
            for (int dx = 0; dx < 5; dx++) {
                const int ix = lx0 + dx;
                const float cx = (ix + 0.5f) * s;
                const float ddx = cx - gcx;
                const float nrm = sqrtf(__fadd_rn(__fmul_rn(ddx, ddx), ddy2));
                const int idx = offs[l] + iy * n + ix;
                if (nrm < td[8] || (nrm == td[8] && idx < ti[8])) {
                    float vd = nrm; int vi = idx;
#pragma unroll
                    for (int k = 0; k < 9; k++) {
                        bool lt = (vd < td[k]) || (vd == td[k] && vi < ti[k]);
                        if (lt) {
                            float tf = td[k]; td[k] = vd; vd = tf;
                            int   tn = ti[k]; ti[k] = vi; vi = tn;
                        }
                    }
                }
            }
        }
    }

    // IoU of the 9 selected anchors (reconstruct boxes analytically)
    const float area_g = (gt.z - gt.x) * (gt.w - gt.y);
    float vals[9];
#pragma unroll
    for (int k = 0; k < 9; k++) {
        int idx = ti[k];
        int l = 0;
#pragma unroll
        for (int q = 1; q < 5; q++) if (idx >= offs[q]) l = q;
        const int r = idx - offs[l];
        const int n = ns[l];
        const float s = ss[l];
        const int iy = r / n, ix = r - iy * n;
        const float cx = (ix + 0.5f) * s, cy = (iy + 0.5f) * s;
        const float half = 2.0f * s;
        const float ax = cx - half, ay = cy - half, az = cx + half, aw = cy + half;
        const float area_a = (az - ax) * (aw - ay);
        const float lx = fmaxf(ax, gt.x), ly = fmaxf(ay, gt.y);
        const float rx = fminf(az, gt.z), ry = fminf(aw, gt.w);
        const float iw = fmaxf(rx - lx, 0.f), ih = fmaxf(ry - ly, 0.f);
        const float inter = iw * ih;
        const float uni = area_a + area_g - inter;
        vals[k] = inter / fmaxf(uni, 1e-9f);
    }

    float sum = 0.f;
#pragma unroll
    for (int k = 0; k < 9; k++) sum += vals[k];
    const float mean = sum / 9.0f;
    float vs = 0.f;
#pragma unroll
    for (int k = 0; k < 9; k++) { float t = vals[k] - mean; vs += t * t; }
    g_thr[g] = mean + sqrtf(vs / 8.0f);
}

// ---------------------------------------------------------------------------
// Phase B: fused match + QFL + DFL + GIoU. One thread per (b, n).
// Division-free match loop, fast-math QFL, positives-only reg path.
// ---------------------------------------------------------------------------
__global__ void loss_kernel(const float* __restrict__ cls_preds,
                            const float* __restrict__ reg_preds,
                            const float4* __restrict__ anchors,
                            const float4* __restrict__ gt_boxes,
                            const int* __restrict__ gt_labels) {
    __shared__ float4 sGT[MGT];
    __shared__ float  sThr[MGT];
    __shared__ float  sArea[MGT];
    __shared__ int    sLab[MGT];
    const int b = blockIdx.y;
    if (threadIdx.x < MGT) {
        float4 gbx = gt_boxes[b * MGT + threadIdx.x];
        sGT[threadIdx.x]   = gbx;
        sArea[threadIdx.x] = (gbx.z - gbx.x) * (gbx.w - gbx.y);
        sThr[threadIdx.x]  = g_thr[b * MGT + threadIdx.x];
        sLab[threadIdx.x]  = gt_labels[b * MGT + threadIdx.x];
    }
    __syncthreads();

    const int n = blockIdx.x * blockDim.x + threadIdx.x;
    float qfl = 0.f, dfl = 0.f, giou_l = 0.f;
    int posi = 0;

    if (n < NANCH) {
        const float4 a = __ldg(&anchors[n]);
        const float aw = a.z - a.x, ah = a.w - a.y;
        const float acx = a.x + 0.5f * aw, acy = a.y + 0.5f * ah;
        const float area_a = aw * ah;

        int matched = -1;
        float m_inter = 0.f, m_uni = 1.f;
#pragma unroll 4
        for (int m = 0; m < MGT; m++) {
            const float4 gbx = sGT[m];
            const float lx = fmaxf(a.x, gbx.x), ly = fmaxf(a.y, gbx.y);
            const float rx = fminf(a.z, gbx.z), ry = fminf(a.w, gbx.w);
            const float iw = fmaxf(rx - lx, 0.f), ih = fmaxf(ry - ly, 0.f);
            const float inter = iw * ih;
            const float uni = area_a + sArea[m] - inter;
            const bool inside = (acx >= gbx.x) && (acx <= gbx.z) &&
                                (acy >= gbx.y) && (acy <= gbx.w);
            if (inside && inter >= sThr[m] * uni) {
                matched = m; m_inter = inter; m_uni = uni;
            }
        }
        const bool pos = matched >= 0;
        posi = pos ? 1 : 0;
        const float it = pos ? (m_inter / fmaxf(m_uni, 1e-9f)) : 0.f;
        const int cls_t = pos ? sLab[matched] : 0;
        const float4 rt = pos ? sGT[matched] : make_float4(0.f, 0.f, 0.f, 0.f);

        // ---- Quality Focal Loss over 20 classes (fast-math) ----
        const float4* cp = (const float4*)(cls_preds + ((size_t)b * NANCH + n) * NCLS);
#pragma unroll
        for (int v = 0; v < 5; v++) {
            const float4 xv = __ldg(&cp[v]);
            const float xs[4] = { xv.x, xv.y, xv.z, xv.w };
#pragma unroll
            for (int j = 0; j < 4; j++) {
                const int c = v * 4 + j;
                const float x = xs[j];
                const bool tpos = (c == cls_t);
                const float e = __expf(-fabsf(x));
                const float sp = __logf(1.0f + e);               // log1p(exp(-|x|))
                const float r = __fdividef(1.0f, 1.0f + e);
                const float psig = (x >= 0.f) ? r : (1.0f - r);  // sigmoid(x)
                const float pt = tpos ? psig : (1.0f - psig);
                const float bce = fmaxf(x, 0.f) - (tpos ? x : 0.f) + sp;
                const float w = fmaf(it, 1.0f - 2.0f * pt, pt);  // it*(1-pt)+(1-it)*pt
                qfl += w * w * bce;
            }
        }

        // ---- DFL + decode + GIoU: positives only ----
        if (pos) {
            const float4* rp = (const float4*)(reg_preds + ((size_t)b * NANCH + n) * 4 * NBINS);
            const float rts[4] = { rt.x, rt.y, rt.z, rt.w };
            float delta[4];
#pragma unroll
            for (int s = 0; s < 4; s++) {
                float l[16];
#pragma unroll
                for (int v = 0; v < 4; v++) {
                    const float4 lv = __ldg(&rp[s * 4 + v]);
                    l[v * 4 + 0] = lv.x; l[v * 4 + 1] = lv.y;
                    l[v * 4 + 2] = lv.z; l[v * 4 + 3] = lv.w;
                }
                float mx = l[0];
#pragma unroll
                for (int k = 1; k < 16; k++) mx = fmaxf(mx, l[k]);

                const float ts = rts[s] * 15.f;
                int li = (int)ts; li = max(0, min(li, 14));
                const int ri = li + 1;
                const float wr = ts - (float)li, wl = 1.f - wr;

                float se = 0.f, ne = 0.f, lli = 0.f, lri = 0.f;
#pragma unroll
                for (int k = 0; k < 16; k++) {
                    const float ek = expf(l[k] - mx);
                    se += ek; ne += ek * (float)k;
                    if (k == li) lli = l[k];
                    if (k == ri) lri = l[k];
                }
                const float lz = mx + logf(se);
                dfl += -(wl * (lli - lz) + wr * (lri - lz));
                delta[s] = ne / (se * 15.f);
            }
            // delta2bbox
            const float pcx = delta[0] * aw + acx;
            const float pcy = delta[1] * ah + acy;
            const float pw = expf(delta[2]) * aw;
            const float ph = expf(delta[3]) * ah;
            const float px1 = pcx - 0.5f * pw, py1 = pcy - 0.5f * ph;
            const float px2 = pcx + 0.5f * pw, py2 = pcy + 0.5f * ph;
            // elementwise giou
            const float lx = fmaxf(px1, rt.x), ly = fmaxf(py1, rt.y);
            const float rx = fminf(px2, rt.z), ry = fminf(py2, rt.w);
            const float iw = fmaxf(rx - lx, 0.f), ih = fmaxf(ry - ly, 0.f);
            const float inter = iw * ih;
            const float pa = (px2 - px1) * (py2 - py1);
            const float ga = (rt.z - rt.x) * (rt.w - rt.y);
            const float uni = pa + ga - inter;
            const float iou = inter / fmaxf(uni, 1e-9f);
            const float ex1 = fminf(px1, rt.x), ey1 = fminf(py1, rt.y);
            const float ex2 = fmaxf(px2, rt.z), ey2 = fmaxf(py2, rt.w);
            const float ew = fmaxf(ex2 - ex1, 0.f), eh = fmaxf(ey2 - ey1, 0.f);
            const float enc = ew * eh;
            const float gv = iou - (enc - uni) / fmaxf(enc, 1e-9f);
            giou_l = 1.f - gv;
        }
    }

    // ---- reduction: warp -> block -> global double atomics ----
#pragma unroll
    for (int off = 16; off > 0; off >>= 1) {
        qfl    += __shfl_xor_sync(0xffffffffu, qfl,    off);
        dfl    += __shfl_xor_sync(0xffffffffu, dfl,    off);
        giou_l += __shfl_xor_sync(0xffffffffu, giou_l, off);
        posi   += __shfl_xor_sync(0xffffffffu, posi,   off);
    }
    __shared__ float rq[8], rd[8], rg[8];
    __shared__ int   rp_[8];
    const int warp = threadIdx.x >> 5;
    const int lane = threadIdx.x & 31;
    if (lane == 0) { rq[warp] = qfl; rd[warp] = dfl; rg[warp] = giou_l; rp_[warp] = posi; }
    __syncthreads();
    if (threadIdx.x == 0) {
        float q = 0.f, dd = 0.f, gg = 0.f; int pp = 0;
#pragma unroll
        for (int wi = 0; wi < LOSS_BLK / 32; wi++) {
            q += rq[wi]; dd += rd[wi]; gg += rg[wi]; pp += rp_[wi];
        }
        if (q  != 0.f) atomicAdd(&g_qfl,  (double)q);
        if (dd != 0.f) atomicAdd(&g_dfl,  (double)dd);
        if (gg != 0.f) atomicAdd(&g_giou, (double)gg);
        if (pp != 0)   atomicAdd(&g_pos,  pp);
    }
}

__global__ void final_kernel(float* __restrict__ out) {
    const int pos = g_pos;
    const double npc = (double)max(pos, 1);
    const double qv = g_qfl / npc;
    double df = g_dfl / (double)max(4 * pos, 1);
    df = fmin(fmax(df, 0.0), 1.0);
    const double gi = g_giou / npc;
    out[0] = (float)(qv + df + gi);
    out[1] = (float)qv;
    out[2] = (float)df;
    out[3] = (float)gi;
}

extern "C" void kernel_launch(void* const* d_in, const int* in_sizes, int n_in,
                              void* d_out, int out_size) {
    const float*  cls_preds = (const float*)d_in[0];
    const float*  reg_preds = (const float*)d_in[1];
    const float4* anchors   = (const float4*)d_in[2];
    const float4* gt_boxes  = (const float4*)d_in[3];
    const int*    gt_labels = (const int*)d_in[4];
    float* out = (float*)d_out;

    thr_kernel<<<2, 256>>>(gt_boxes);
    dim3 grid(LOSS_GX, BATCH);
    loss_kernel<<<grid, LOSS_BLK>>>(cls_preds, reg_preds, anchors, gt_boxes, gt_labels);
    final_kernel<<<1, 1>>>(out);
}

// round 7
// speedup vs baseline: 4.4870x; 1.8892x over previous
#include <cuda_runtime.h>
#include <math.h>

#define NCLS   20
#define NBINS  16
#define NANCH  21824
#define BATCH  16
#define MGT    32
#define NGT    (BATCH*MGT)

#define LOSS_BLK   256
#define LOSS_GX    ((NANCH + LOSS_BLK - 1) / LOSS_BLK)   // 86

// global accumulators / scratch (no device mallocs allowed)
__device__ double g_qfl, g_dfl, g_giou;
__device__ int    g_pos;
__device__ float  g_thr[NGT];

// ---------------------------------------------------------------------------
// Phase A: ATSS threshold, one WARP per GT using analytic grid candidates.
// The 9 nearest anchors to any point lie within the 5x5 cell window around
// the containing cell at every level (anchor centers are regular grids).
// 125 candidates are spread across the 32 lanes (<=4 each); the global top-9
// by lexicographic (dist, idx) — matching jax.lax.top_k tie-breaking — is
// found with 9 rounds of warp butterfly argmin. Lanes 0..8 then compute the
// 9 IoUs; mean/std are evaluated in the exact sequential order of the
// previously-validated scalar version, so thresholds are bit-identical.
// ---------------------------------------------------------------------------
__global__ void thr_kernel(const float4* __restrict__ gt_boxes) {
    const int warp = threadIdx.x >> 5;
    const int lane = threadIdx.x & 31;
    const int g = blockIdx.x * 8 + warp;            // 0..511
    if (blockIdx.x == 0 && threadIdx.x == 0) {
        g_qfl = 0.0; g_dfl = 0.0; g_giou = 0.0; g_pos = 0;
    }
    if (g >= NGT) return;

    const float4 gt = __ldg(&gt_boxes[g]);
    const float gcx = 0.5f * (gt.x + gt.z);
    const float gcy = 0.5f * (gt.y + gt.w);

    // each lane evaluates candidates c = lane + 32*j, j=0..3 (125 total)
    float cd[4]; int ci[4];
#pragma unroll
    for (int j = 0; j < 4; j++) {
        const int c = lane + 32 * j;
        float nrm = 3.4e38f; int idx = 0x7fffffff;
        if (c < 125) {
            const int l   = c / 25;
            const int rem = c - 25 * l;
            const int dy  = rem / 5;
            const int dx  = rem - 5 * dy;
            const int   n    = 128 >> l;
            const float s    = (float)(8 << l);
            const int   offs = (65536 - (65536 >> (2 * l))) / 3;
            const int jcx = (int)floorf(gcx / s);
            const int jcy = (int)floorf(gcy / s);
            const int lx0 = min(max(jcx - 2, 0), n - 5);
            const int ly0 = min(max(jcy - 2, 0), n - 5);
            const int ix = lx0 + dx;
            const int iy = ly0 + dy;
            const float cx = (ix + 0.5f) * s;
            const float cy = (iy + 0.5f) * s;
            const float ddx = cx - gcx;
            const float ddy = cy - gcy;
            const float ddy2 = __fmul_rn(ddy, ddy);
            nrm = sqrtf(__fadd_rn(__fmul_rn(ddx, ddx), ddy2));
            idx = offs + iy * n + ix;
        }
        cd[j] = nrm; ci[j] = idx;
    }

    // 9 rounds of warp-wide lexicographic argmin; winners land in ascending
    // (dist, idx) order. Lane r keeps round-r winner's index in my_win.
    int my_win = 0;
#pragma unroll
    for (int r = 0; r < 9; r++) {
        // lane-local best among unused slots
        float bd = cd[0]; int bi = ci[0]; int bs = 0;
#pragma unroll
        for (int k = 1; k < 4; k++) {
            const bool lt = (cd[k] < bd) || (cd[k] == bd && ci[k] < bi);
            if (lt) { bd = cd[k]; bi = ci[k]; bs = k; }
        }
        // butterfly argmin across the warp
        float wd = bd; int wi = bi;
#pragma unroll
        for (int off = 16; off > 0; off >>= 1) {
            const float od = __shfl_xor_sync(0xffffffffu, wd, off);
            const int   oi = __shfl_xor_sync(0xffffffffu, wi, off);
            if (od < wd || (od == wd && oi < wi)) { wd = od; wi = oi; }
        }
        if (lane == r) my_win = wi;
        // owner retires its winning slot
        if (bi == wi) {
#pragma unroll
            for (int k = 0; k < 4; k++)
                if (k == bs) { cd[k] = 3.4e38f; ci[k] = 0x7fffffff; }
        }
    }

    // lanes 0..8: IoU of their winner anchor with the GT
    const float area_g = (gt.z - gt.x) * (gt.w - gt.y);
    float iou = 0.f;
    if (lane < 9) {
        const int idx = my_win;
        const int l = (idx >= 16384) + (idx >= 20480) + (idx >= 21504) + (idx >= 21760);
        const int   n    = 128 >> l;
        const float s    = (float)(8 << l);
        const int   offs = (65536 - (65536 >> (2 * l))) / 3;
        const int r = idx - offs;
        const int iy = r / n, ix = r - iy * n;
        const float cx = (ix + 0.5f) * s, cy = (iy + 0.5f) * s;
        const float half = 2.0f * s;
        const float ax = cx - half, ay = cy - half, az = cx + half, aw = cy + half;
        const float area_a = (az - ax) * (aw - ay);
        const float lx = fmaxf(ax, gt.x), ly = fmaxf(ay, gt.y);
        const float rx = fminf(az, gt.z), ry = fminf(aw, gt.w);
        const float iw = fmaxf(rx - lx, 0.f), ih = fmaxf(ry - ly, 0.f);
        const float inter = iw * ih;
        const float uni = area_a + area_g - inter;
        iou = inter / fmaxf(uni, 1e-9f);
    }

    // broadcast v0..v8 and reduce in the exact sequential order of the
    // validated scalar version (bit-identical thresholds)
    float v[9];
#pragma unroll
    for (int k = 0; k < 9; k++) v[k] = __shfl_sync(0xffffffffu, iou, k);
    if (lane == 0) {
        float sum = 0.f;
#pragma unroll
        for (int k = 0; k < 9; k++) sum += v[k];
        const float mean = sum / 9.0f;
        float vs = 0.f;
#pragma unroll
        for (int k = 0; k < 9; k++) { const float t = v[k] - mean; vs += t * t; }
        g_thr[g] = mean + sqrtf(vs / 8.0f);
    }
}

// ---------------------------------------------------------------------------
// Phase B: fused match + QFL + DFL + GIoU. One thread per (b, n).
// Division-free match loop, fast-math QFL, positives-only reg path.
// ---------------------------------------------------------------------------
__global__ void loss_kernel(const float* __restrict__ cls_preds,
                            const float* __restrict__ reg_preds,
                            const float4* __restrict__ anchors,
                            const float4* __restrict__ gt_boxes,
                            const int* __restrict__ gt_labels) {
    __shared__ float4 sGT[MGT];
    __shared__ float  sThr[MGT];
    __shared__ float  sArea[MGT];
    __shared__ int    sLab[MGT];
    const int b = blockIdx.y;
    if (threadIdx.x < MGT) {
        float4 gbx = gt_boxes[b * MGT + threadIdx.x];
        sGT[threadIdx.x]   = gbx;
        sArea[threadIdx.x] = (gbx.z - gbx.x) * (gbx.w - gbx.y);
        sThr[threadIdx.x]  = g_thr[b * MGT + threadIdx.x];
        sLab[threadIdx.x]  = gt_labels[b * MGT + threadIdx.x];
    }
    __syncthreads();

    const int n = blockIdx.x * blockDim.x + threadIdx.x;
    float qfl = 0.f, dfl = 0.f, giou_l = 0.f;
    int posi = 0;

    if (n < NANCH) {
        const float4 a = __ldg(&anchors[n]);
        const float aw = a.z - a.x, ah = a.w - a.y;
        const float acx = a.x + 0.5f * aw, acy = a.y + 0.5f * ah;
        const float area_a = aw * ah;

        int matched = -1;
        float m_inter = 0.f, m_uni = 1.f;
#pragma unroll 4
        for (int m = 0; m < MGT; m++) {
            const float4 gbx = sGT[m];
            const float lx = fmaxf(a.x, gbx.x), ly = fmaxf(a.y, gbx.y);
            const float rx = fminf(a.z, gbx.z), ry = fminf(a.w, gbx.w);
            const float iw = fmaxf(rx - lx, 0.f), ih = fmaxf(ry - ly, 0.f);
            const float inter = iw * ih;
            const float uni = area_a + sArea[m] - inter;
            const bool inside = (acx >= gbx.x) && (acx <= gbx.z) &&
                                (acy >= gbx.y) && (acy <= gbx.w);
            if (inside && inter >= sThr[m] * uni) {
                matched = m; m_inter = inter; m_uni = uni;
            }
        }
        const bool pos = matched >= 0;
        posi = pos ? 1 : 0;
        const float it = pos ? (m_inter / fmaxf(m_uni, 1e-9f)) : 0.f;
        const int cls_t = pos ? sLab[matched] : 0;
        const float4 rt = pos ? sGT[matched] : make_float4(0.f, 0.f, 0.f, 0.f);

        // ---- Quality Focal Loss over 20 classes (fast-math) ----
        const float4* cp = (const float4*)(cls_preds + ((size_t)b * NANCH + n) * NCLS);
#pragma unroll
        for (int v = 0; v < 5; v++) {
            const float4 xv = __ldg(&cp[v]);
            const float xs[4] = { xv.x, xv.y, xv.z, xv.w };
#pragma unroll
            for (int j = 0; j < 4; j++) {
                const int c = v * 4 + j;
                const float x = xs[j];
                const bool tpos = (c == cls_t);
                const float e = __expf(-fabsf(x));
                const float sp = __logf(1.0f + e);               // log1p(exp(-|x|))
                const float r = __fdividef(1.0f, 1.0f + e);
                const float psig = (x >= 0.f) ? r : (1.0f - r);  // sigmoid(x)
                const float pt = tpos ? psig : (1.0f - psig);
                const float bce = fmaxf(x, 0.f) - (tpos ? x : 0.f) + sp;
                const float w = fmaf(it, 1.0f - 2.0f * pt, pt);  // it*(1-pt)+(1-it)*pt
                qfl += w * w * bce;
            }
        }

        // ---- DFL + decode + GIoU: positives only ----
        if (pos) {
            const float4* rp = (const float4*)(reg_preds + ((size_t)b * NANCH + n) * 4 * NBINS);
            const float rts[4] = { rt.x, rt.y, rt.z, rt.w };
            float delta[4];
#pragma unroll
            for (int s = 0; s < 4; s++) {
                float l[16];
#pragma unroll
                for (int v = 0; v < 4; v++) {
                    const float4 lv = __ldg(&rp[s * 4 + v]);
                    l[v * 4 + 0] = lv.x; l[v * 4 + 1] = lv.y;
                    l[v * 4 + 2] = lv.z; l[v * 4 + 3] = lv.w;
                }
                float mx = l[0];
#pragma unroll
                for (int k = 1; k < 16; k++) mx = fmaxf(mx, l[k]);

                const float ts = rts[s] * 15.f;
                int li = (int)ts; li = max(0, min(li, 14));
                const int ri = li + 1;
                const float wr = ts - (float)li, wl = 1.f - wr;

                float se = 0.f, ne = 0.f, lli = 0.f, lri = 0.f;
#pragma unroll
                for (int k = 0; k < 16; k++) {
                    const float ek = expf(l[k] - mx);
                    se += ek; ne += ek * (float)k;
                    if (k == li) lli = l[k];
                    if (k == ri) lri = l[k];
                }
                const float lz = mx + logf(se);
                dfl += -(wl * (lli - lz) + wr * (lri - lz));
                delta[s] = ne / (se * 15.f);
            }
            // delta2bbox
            const float pcx = delta[0] * aw + acx;
            const float pcy = delta[1] * ah + acy;
            const float pw = expf(delta[2]) * aw;
            const float ph = expf(delta[3]) * ah;
            const float px1 = pcx - 0.5f * pw, py1 = pcy - 0.5f * ph;
            const float px2 = pcx + 0.5f * pw, py2 = pcy + 0.5f * ph;
            // elementwise giou
            const float lx = fmaxf(px1, rt.x), ly = fmaxf(py1, rt.y);
            const float rx = fminf(px2, rt.z), ry = fminf(py2, rt.w);
            const float iw = fmaxf(rx - lx, 0.f), ih = fmaxf(ry - ly, 0.f);
            const float inter = iw * ih;
            const float pa = (px2 - px1) * (py2 - py1);
            const float ga = (rt.z - rt.x) * (rt.w - rt.y);
            const float uni = pa + ga - inter;
            const float iou = inter / fmaxf(uni, 1e-9f);
            const float ex1 = fminf(px1, rt.x), ey1 = fminf(py1, rt.y);
            const float ex2 = fmaxf(px2, rt.z), ey2 = fmaxf(py2, rt.w);
            const float ew = fmaxf(ex2 - ex1, 0.f), eh = fmaxf(ey2 - ey1, 0.f);
            const float enc = ew * eh;
            const float gv = iou - (enc - uni) / fmaxf(enc, 1e-9f);
            giou_l = 1.f - gv;
        }
    }

    // ---- reduction: warp -> block -> global double atomics ----
#pragma unroll
    for (int off = 16; off > 0; off >>= 1) {
        qfl    += __shfl_xor_sync(0xffffffffu, qfl,    off);
        dfl    += __shfl_xor_sync(0xffffffffu, dfl,    off);
        giou_l += __shfl_xor_sync(0xffffffffu, giou_l, off);
        posi   += __shfl_xor_sync(0xffffffffu, posi,   off);
    }
    __shared__ float rq[8], rd[8], rg[8];
    __shared__ int   rp_[8];
    const int warp = threadIdx.x >> 5;
    const int lane = threadIdx.x & 31;
    if (lane == 0) { rq[warp] = qfl; rd[warp] = dfl; rg[warp] = giou_l; rp_[warp] = posi; }
    __syncthreads();
    if (threadIdx.x == 0) {
        float q = 0.f, dd = 0.f, gg = 0.f; int pp = 0;
#pragma unroll
        for (int wi = 0; wi < LOSS_BLK / 32; wi++) {
            q += rq[wi]; dd += rd[wi]; gg += rg[wi]; pp += rp_[wi];
        }
        if (q  != 0.f) atomicAdd(&g_qfl,  (double)q);
        if (dd != 0.f) atomicAdd(&g_dfl,  (double)dd);
        if (gg != 0.f) atomicAdd(&g_giou, (double)gg);
        if (pp != 0)   atomicAdd(&g_pos,  pp);
    }
}

__global__ void final_kernel(float* __restrict__ out) {
    const int pos = g_pos;
    const double npc = (double)max(pos, 1);
    const double qv = g_qfl / npc;
    double df = g_dfl / (double)max(4 * pos, 1);
    df = fmin(fmax(df, 0.0), 1.0);
    const double gi = g_giou / npc;
    out[0] = (float)(qv + df + gi);
    out[1] = (float)qv;
    out[2] = (float)df;
    out[3] = (float)gi;
}

extern "C" void kernel_launch(void* const* d_in, const int* in_sizes, int n_in,
                              void* d_out, int out_size) {
    const float*  cls_preds = (const float*)d_in[0];
    const float*  reg_preds = (const float*)d_in[1];
    const float4* anchors   = (const float4*)d_in[2];
    const float4* gt_boxes  = (const float4*)d_in[3];
    const int*    gt_labels = (const int*)d_in[4];
    float* out = (float*)d_out;

    thr_kernel<<<64, 256>>>(gt_boxes);
    dim3 grid(LOSS_GX, BATCH);
    loss_kernel<<<grid, LOSS_BLK>>>(cls_preds, reg_preds, anchors, gt_boxes, gt_labels);
    final_kernel<<<1, 1>>>(out);
}